// round 1
// baseline (speedup 1.0000x reference)
#include <cuda_runtime.h>

#define NU 200000
#define NI 100000
#define D  64
#define NU4 (NU * (D / 4))   // 3,200,000 float4 per user buffer
#define NI4 (NI * (D / 4))   // 1,600,000 float4 per item buffer
#define EMAX 2000000

// Scratch (static device globals — allocation-free, reused pos then neg)
__device__ float4 g_u0[NU4];
__device__ float4 g_u1[NU4];
__device__ float4 g_i0[NI4];
__device__ float4 g_i1[NI4];
__device__ float  g_degu[NU];
__device__ float  g_degi[NI];
__device__ float  g_norm[EMAX];

__device__ __forceinline__ void red4(float4* p, float4 v) {
    asm volatile("red.global.add.v4.f32 [%0], {%1,%2,%3,%4};"
                 :: "l"(__cvta_generic_to_global(p)),
                    "f"(v.x), "f"(v.y), "f"(v.z), "f"(v.w)
                 : "memory");
}

__global__ void k_zero_deg() {
    int i = blockIdx.x * blockDim.x + threadIdx.x;
    if (i < NU) g_degu[i] = 0.f;
    if (i < NI) g_degi[i] = 0.f;
}

__global__ void k_count(const int* __restrict__ row, const int* __restrict__ col, int E) {
    int e = blockIdx.x * blockDim.x + threadIdx.x;
    if (e < E) {
        atomicAdd(&g_degu[row[e]], 1.f);
        atomicAdd(&g_degi[col[e]], 1.f);
    }
}

__global__ void k_rsqrt() {
    int i = blockIdx.x * blockDim.x + threadIdx.x;
    if (i < NU) g_degu[i] = rsqrtf(fmaxf(g_degu[i], 1.f));
    if (i < NI) g_degi[i] = rsqrtf(fmaxf(g_degi[i], 1.f));
}

__global__ void k_norm(const int* __restrict__ row, const int* __restrict__ col,
                       const float* __restrict__ w, int E) {
    int e = blockIdx.x * blockDim.x + threadIdx.x;
    if (e < E) {
        float wv = w ? w[e] : 1.f;
        g_norm[e] = g_degu[row[e]] * g_degi[col[e]] * wv;
    }
}

// cur = nxt = emb ; sum = emb * inv
__global__ void k_init(const float4* __restrict__ ue, const float4* __restrict__ ie,
                       float4* __restrict__ su, float4* __restrict__ si, float inv) {
    int i = blockIdx.x * blockDim.x + threadIdx.x;
    if (i < NU4) {
        float4 v = ue[i];
        g_u0[i] = v; g_u1[i] = v;
        su[i] = make_float4(v.x * inv, v.y * inv, v.z * inv, v.w * inv);
    } else if (i < NU4 + NI4) {
        int j = i - NU4;
        float4 v = ie[j];
        g_i0[j] = v; g_i1[j] = v;
        si[j] = make_float4(v.x * inv, v.y * inv, v.z * inv, v.w * inv);
    }
}

// One edge per 16 threads; each thread owns 4 consecutive floats (float4).
// Reads cur (parity p), red.v4 accumulates into nxt (parity p^1), which was
// pre-initialized equal to cur — so nxt ends as cur + aggregated neighbors.
__global__ void k_scatter(const int* __restrict__ row, const int* __restrict__ col,
                          int E, int p) {
    int e = blockIdx.x * 16 + (threadIdx.x >> 4);
    if (e >= E) return;
    int t = threadIdx.x & 15;

    const float4* cu = p ? g_u1 : g_u0;
    const float4* ci = p ? g_i1 : g_i0;
    float4* nu = p ? g_u0 : g_u1;
    float4* ni = p ? g_i0 : g_i1;

    int   r = __ldg(row + e);
    int   c = __ldg(col + e);
    float n = __ldg(g_norm + e);

    float4 iv = __ldg(ci + c * 16 + t);
    red4(nu + r * 16 + t, make_float4(iv.x * n, iv.y * n, iv.z * n, iv.w * n));

    float4 uv = __ldg(cu + r * 16 + t);
    red4(ni + c * 16 + t, make_float4(uv.x * n, uv.y * n, uv.z * n, uv.w * n));
}

// sum += nxt * inv ; other buffer := nxt (prepares next layer's accumulator)
__global__ void k_accum(float4* __restrict__ su, float4* __restrict__ si,
                        int p, float inv) {
    int i = blockIdx.x * blockDim.x + threadIdx.x;
    if (i < NU4) {
        float4 v = (p ? g_u0 : g_u1)[i];
        (p ? g_u1 : g_u0)[i] = v;
        float4 s = su[i];
        su[i] = make_float4(s.x + v.x * inv, s.y + v.y * inv,
                            s.z + v.z * inv, s.w + v.w * inv);
    } else if (i < NU4 + NI4) {
        int j = i - NU4;
        float4 v = (p ? g_i0 : g_i1)[j];
        (p ? g_i1 : g_i0)[j] = v;
        float4 s = si[j];
        si[j] = make_float4(s.x + v.x * inv, s.y + v.y * inv,
                            s.z + v.z * inv, s.w + v.w * inv);
    }
}

extern "C" void kernel_launch(void* const* d_in, const int* in_sizes, int n_in,
                              void* d_out, int out_size) {
    const int*   ei  = (const int*)d_in[0];
    const int*   nei = (const int*)d_in[1];
    const float* ew  = (const float*)d_in[2];
    const float* up  = (const float*)d_in[3];
    const float* ip  = (const float*)d_in[4];
    const float* un  = (const float*)d_in[5];
    const float* inw = (const float*)d_in[6];
    float* out = (float*)d_out;

    const int Epos = in_sizes[0] / 2;
    const int Eneg = in_sizes[1] / 2;
    const float inv = 1.0f / 5.0f;   // 1/(N_LAYERS+1)

    struct Pass {
        const int* row; const int* col; const float* w; int E;
        const float* eu; const float* eiemb;
        float* su; float* si;
    };
    Pass passes[2];
    passes[0] = { ei,  ei  + Epos, ew,      Epos, up, ip,
                  out,                       out + (size_t)NU * D };
    passes[1] = { nei, nei + Eneg, nullptr, Eneg, un, inw,
                  out + (size_t)(NU + NI) * D, out + (size_t)(2 * NU + NI) * D };

    const int TB = 256;
    const int gDeg  = (NU + TB - 1) / TB;
    const int gEmb  = (NU4 + NI4 + TB - 1) / TB;

    for (int s = 0; s < 2; s++) {
        Pass P = passes[s];
        int gE = (P.E + TB - 1) / TB;

        k_zero_deg<<<gDeg, TB>>>();
        k_count<<<gE, TB>>>(P.row, P.col, P.E);
        k_rsqrt<<<gDeg, TB>>>();
        k_norm<<<gE, TB>>>(P.row, P.col, P.w, P.E);
        k_init<<<gEmb, TB>>>((const float4*)P.eu, (const float4*)P.eiemb,
                             (float4*)P.su, (float4*)P.si, inv);

        int gScat = (P.E + 15) / 16;   // 16 edges per 256-thread block
        for (int l = 0; l < 4; l++) {
            k_scatter<<<gScat, TB>>>(P.row, P.col, P.E, l & 1);
            k_accum<<<gEmb, TB>>>((float4*)P.su, (float4*)P.si, l & 1, inv);
        }
    }
}

// round 2
// speedup vs baseline: 1.6259x; 1.6259x over previous
#include <cuda_runtime.h>

#define NU 200000
#define NI 100000
#define D  64
#define NV 16                 // float4 per embedding row
#define NU4 (NU * NV)
#define NI4 (NI * NV)
#define N_NODES (NU + NI)
#define EMAX 2000000
#define SCAN_ITEMS 1024       // elements per scan-A block
#define MAX_NB 512

// Static device scratch (allocation-free)
__device__ float4 g_u0[NU4];
__device__ float4 g_u1[NU4];
__device__ float4 g_i0[NI4];
__device__ float4 g_i1[NI4];
__device__ int    g_cnt[N_NODES];   // per-node edge counts (== degrees)
__device__ int    g_off[N_NODES];   // exclusive CSR offsets
__device__ int    g_cur[N_NODES];   // fill cursors
__device__ int    g_bsum[MAX_NB];   // scan block sums
__device__ float2 g_pl[2 * EMAX];   // payload: {neighbor idx (bits), norm}

__global__ void k_zero_cnt() {
    int i = blockIdx.x * blockDim.x + threadIdx.x;
    if (i < N_NODES) g_cnt[i] = 0;
}

__global__ void k_count(const int* __restrict__ row, const int* __restrict__ col, int E) {
    int e = blockIdx.x * blockDim.x + threadIdx.x;
    if (e < E) {
        atomicAdd(&g_cnt[row[e]], 1);
        atomicAdd(&g_cnt[NU + col[e]], 1);
    }
}

// --- 3-phase exclusive scan over g_cnt -> g_off ---
__global__ void k_scanA(int n) {
    __shared__ int wsum[8];
    int base = blockIdx.x * SCAN_ITEMS + threadIdx.x * 4;
    int v[4]; int s = 0;
#pragma unroll
    for (int j = 0; j < 4; j++) {
        int idx = base + j;
        v[j] = (idx < n) ? g_cnt[idx] : 0;
        s += v[j];
    }
    int lane = threadIdx.x & 31, warp = threadIdx.x >> 5;
    int incl = s;
#pragma unroll
    for (int o = 1; o < 32; o <<= 1) {
        int t = __shfl_up_sync(~0u, incl, o);
        if (lane >= o) incl += t;
    }
    if (lane == 31) wsum[warp] = incl;
    __syncthreads();
    if (warp == 0 && lane < 8) {
        int ws = wsum[lane];
#pragma unroll
        for (int o = 1; o < 8; o <<= 1) {
            int t = __shfl_up_sync(0xffu, ws, o);
            if (lane >= o) ws += t;
        }
        wsum[lane] = ws;
    }
    __syncthreads();
    int excl = incl - s + (warp ? wsum[warp - 1] : 0);
    int run = excl;
#pragma unroll
    for (int j = 0; j < 4; j++) {
        int idx = base + j;
        if (idx < n) g_off[idx] = run;
        run += v[j];
    }
    if (threadIdx.x == 0) g_bsum[blockIdx.x] = wsum[7];
}

__global__ void k_scanB(int nb) {
    __shared__ int sh[MAX_NB];
    int t = threadIdx.x;
    int v = (t < nb) ? g_bsum[t] : 0;
    sh[t] = v;
    __syncthreads();
    for (int o = 1; o < MAX_NB; o <<= 1) {
        int x = (t >= o) ? sh[t - o] : 0;
        __syncthreads();
        sh[t] += x;
        __syncthreads();
    }
    if (t < nb) g_bsum[t] = sh[t] - v;   // exclusive
}

__global__ void k_scanC(int n) {
    int i = blockIdx.x * blockDim.x + threadIdx.x;
    if (i < n) {
        int o = g_off[i] + g_bsum[i / SCAN_ITEMS];
        g_off[i] = o;
        g_cur[i] = o;
    }
}

// Fill CSR payloads; norm computed from counts (degrees)
__global__ void k_fill(const int* __restrict__ row, const int* __restrict__ col,
                       const float* __restrict__ w, int E) {
    int e = blockIdx.x * blockDim.x + threadIdx.x;
    if (e >= E) return;
    int r = row[e], c = col[e];
    float wv = w ? w[e] : 1.f;
    float nrm = rsqrtf((float)g_cnt[r]) * rsqrtf((float)g_cnt[NU + c]) * wv;
    int p0 = atomicAdd(&g_cur[r], 1);
    g_pl[p0] = make_float2(__int_as_float(c), nrm);
    int p1 = atomicAdd(&g_cur[NU + c], 1);
    g_pl[p1] = make_float2(__int_as_float(r), nrm);
}

// cur(parity 0) = emb ; sum = emb * inv
__global__ void k_init(const float4* __restrict__ ue, const float4* __restrict__ ie,
                       float4* __restrict__ su, float4* __restrict__ si, float inv) {
    int i = blockIdx.x * blockDim.x + threadIdx.x;
    if (i < NU4) {
        float4 v = ue[i];
        g_u0[i] = v;
        su[i] = make_float4(v.x * inv, v.y * inv, v.z * inv, v.w * inv);
    } else if (i < NU4 + NI4) {
        int j = i - NU4;
        float4 v = ie[j];
        g_i0[j] = v;
        si[j] = make_float4(v.x * inv, v.y * inv, v.z * inv, v.w * inv);
    }
}

// One node per 16 threads. Gather neighbors (CSR), write nxt once,
// fuse sum += nxt * inv. Ping-pong buffers by parity p.
__global__ void k_gather(int p, float4* __restrict__ usum, float4* __restrict__ isum,
                         float inv) {
    int gid = blockIdx.x * blockDim.x + threadIdx.x;
    int node = gid >> 4;
    int t = gid & 15;
    if (node >= N_NODES) return;

    const float4* ucur = p ? g_u1 : g_u0;
    const float4* icur = p ? g_i1 : g_i0;
    float4* unxt = p ? g_u0 : g_u1;
    float4* inxt = p ? g_i0 : g_i1;

    int beg = g_off[node];
    int cnt = g_cnt[node];

    const float4* src;
    const float4* own;
    float4* dst;
    float4* sum;
    int li;
    if (node < NU) { li = node;      src = icur; own = ucur; dst = unxt; sum = usum; }
    else           { li = node - NU; src = ucur; own = icur; dst = inxt; sum = isum; }

    float4 acc = own[li * NV + t];
    const float2* pl = g_pl + beg;

    int k = 0;
    for (; k + 2 <= cnt; k += 2) {
        float2 p0 = __ldg(pl + k);
        float2 p1 = __ldg(pl + k + 1);
        int i0 = __float_as_int(p0.x);
        int i1 = __float_as_int(p1.x);
        float4 v0 = __ldg(src + i0 * NV + t);
        float4 v1 = __ldg(src + i1 * NV + t);
        acc.x = fmaf(v0.x, p0.y, fmaf(v1.x, p1.y, acc.x));
        acc.y = fmaf(v0.y, p0.y, fmaf(v1.y, p1.y, acc.y));
        acc.z = fmaf(v0.z, p0.y, fmaf(v1.z, p1.y, acc.z));
        acc.w = fmaf(v0.w, p0.y, fmaf(v1.w, p1.y, acc.w));
    }
    if (k < cnt) {
        float2 p0 = __ldg(pl + k);
        int i0 = __float_as_int(p0.x);
        float4 v0 = __ldg(src + i0 * NV + t);
        acc.x = fmaf(v0.x, p0.y, acc.x);
        acc.y = fmaf(v0.y, p0.y, acc.y);
        acc.z = fmaf(v0.z, p0.y, acc.z);
        acc.w = fmaf(v0.w, p0.y, acc.w);
    }

    dst[li * NV + t] = acc;
    float4 s = sum[li * NV + t];
    sum[li * NV + t] = make_float4(fmaf(acc.x, inv, s.x), fmaf(acc.y, inv, s.y),
                                   fmaf(acc.z, inv, s.z), fmaf(acc.w, inv, s.w));
}

extern "C" void kernel_launch(void* const* d_in, const int* in_sizes, int n_in,
                              void* d_out, int out_size) {
    const int*   ei  = (const int*)d_in[0];
    const int*   nei = (const int*)d_in[1];
    const float* ew  = (const float*)d_in[2];
    const float* up  = (const float*)d_in[3];
    const float* ip  = (const float*)d_in[4];
    const float* un  = (const float*)d_in[5];
    const float* inw = (const float*)d_in[6];
    float* out = (float*)d_out;

    const int Epos = in_sizes[0] / 2;
    const int Eneg = in_sizes[1] / 2;
    const float inv = 1.0f / 5.0f;

    struct Pass {
        const int* row; const int* col; const float* w; int E;
        const float* eu; const float* eiemb;
        float* su; float* si;
    };
    Pass passes[2];
    passes[0] = { ei,  ei  + Epos, ew,      Epos, up, ip,
                  out,                        out + (size_t)NU * D };
    passes[1] = { nei, nei + Eneg, nullptr, Eneg, un, inw,
                  out + (size_t)(NU + NI) * D, out + (size_t)(2 * NU + NI) * D };

    const int TB = 256;
    const int gNode = (N_NODES + TB - 1) / TB;
    const int gEmb  = (NU4 + NI4 + TB - 1) / TB;
    const int NB    = (N_NODES + SCAN_ITEMS - 1) / SCAN_ITEMS;   // 293
    const int gGath = (N_NODES * 16 + TB - 1) / TB;

    for (int s = 0; s < 2; s++) {
        Pass P = passes[s];
        int gE = (P.E + TB - 1) / TB;

        k_zero_cnt<<<gNode, TB>>>();
        k_count<<<gE, TB>>>(P.row, P.col, P.E);
        k_scanA<<<NB, 256>>>(N_NODES);
        k_scanB<<<1, MAX_NB>>>(NB);
        k_scanC<<<gNode, TB>>>(N_NODES);
        k_fill<<<gE, TB>>>(P.row, P.col, P.w, P.E);
        k_init<<<gEmb, TB>>>((const float4*)P.eu, (const float4*)P.eiemb,
                             (float4*)P.su, (float4*)P.si, inv);

        for (int l = 0; l < 4; l++)
            k_gather<<<gGath, TB>>>(l & 1, (float4*)P.su, (float4*)P.si, inv);
    }
}

// round 3
// speedup vs baseline: 2.3330x; 1.4349x over previous
#include <cuda_runtime.h>
#include <cuda_fp16.h>

#define NU 200000
#define NI 100000
#define D  64
#define NN (NU + NI)
#define EMAX 2000000
#define SCAN_ITEMS 1024
#define MAX_NB 512

// fp16 layer buffers: row = 64 halves = 128B = 8 uint4 per node. e[0..4].
__device__ __align__(16) uint4 g_e[5][NN * 8];
__device__ int    g_cnt[NN];
__device__ int    g_off[NN];
__device__ int    g_cur[NN];
__device__ int    g_bsum[MAX_NB];
__device__ float2 g_pl[2 * EMAX];   // {neighbor global-node idx (bits), norm}

__device__ __forceinline__ uint4 pack8(const float4& a, const float4& b) {
    __half2 h0 = __floats2half2_rn(a.x, a.y);
    __half2 h1 = __floats2half2_rn(a.z, a.w);
    __half2 h2 = __floats2half2_rn(b.x, b.y);
    __half2 h3 = __floats2half2_rn(b.z, b.w);
    uint4 r;
    r.x = *(unsigned*)&h0; r.y = *(unsigned*)&h1;
    r.z = *(unsigned*)&h2; r.w = *(unsigned*)&h3;
    return r;
}

__device__ __forceinline__ void unpack8(uint4 v, float4& a, float4& b) {
    __half2* hp = (__half2*)&v;
    float2 f0 = __half22float2(hp[0]);
    float2 f1 = __half22float2(hp[1]);
    float2 f2 = __half22float2(hp[2]);
    float2 f3 = __half22float2(hp[3]);
    a = make_float4(f0.x, f0.y, f1.x, f1.y);
    b = make_float4(f2.x, f2.y, f3.x, f3.y);
}

__global__ void k_zero_cnt() {
    int i = blockIdx.x * blockDim.x + threadIdx.x;
    if (i < NN) g_cnt[i] = 0;
}

__global__ void k_count(const int* __restrict__ row, const int* __restrict__ col, int E) {
    int e = blockIdx.x * blockDim.x + threadIdx.x;
    if (e < E) {
        atomicAdd(&g_cnt[row[e]], 1);
        atomicAdd(&g_cnt[NU + col[e]], 1);
    }
}

__global__ void k_scanA(int n) {
    __shared__ int wsum[8];
    int base = blockIdx.x * SCAN_ITEMS + threadIdx.x * 4;
    int v[4]; int s = 0;
#pragma unroll
    for (int j = 0; j < 4; j++) {
        int idx = base + j;
        v[j] = (idx < n) ? g_cnt[idx] : 0;
        s += v[j];
    }
    int lane = threadIdx.x & 31, warp = threadIdx.x >> 5;
    int incl = s;
#pragma unroll
    for (int o = 1; o < 32; o <<= 1) {
        int t = __shfl_up_sync(~0u, incl, o);
        if (lane >= o) incl += t;
    }
    if (lane == 31) wsum[warp] = incl;
    __syncthreads();
    if (warp == 0 && lane < 8) {
        int ws = wsum[lane];
#pragma unroll
        for (int o = 1; o < 8; o <<= 1) {
            int t = __shfl_up_sync(0xffu, ws, o);
            if (lane >= o) ws += t;
        }
        wsum[lane] = ws;
    }
    __syncthreads();
    int excl = incl - s + (warp ? wsum[warp - 1] : 0);
    int run = excl;
#pragma unroll
    for (int j = 0; j < 4; j++) {
        int idx = base + j;
        if (idx < n) g_off[idx] = run;
        run += v[j];
    }
    if (threadIdx.x == 0) g_bsum[blockIdx.x] = wsum[7];
}

__global__ void k_scanB(int nb) {
    __shared__ int sh[MAX_NB];
    int t = threadIdx.x;
    int v = (t < nb) ? g_bsum[t] : 0;
    sh[t] = v;
    __syncthreads();
    for (int o = 1; o < MAX_NB; o <<= 1) {
        int x = (t >= o) ? sh[t - o] : 0;
        __syncthreads();
        sh[t] += x;
        __syncthreads();
    }
    if (t < nb) g_bsum[t] = sh[t] - v;
}

__global__ void k_scanC(int n) {
    int i = blockIdx.x * blockDim.x + threadIdx.x;
    if (i < n) {
        int o = g_off[i] + g_bsum[i / SCAN_ITEMS];
        g_off[i] = o;
        g_cur[i] = o;
    }
}

__global__ void k_fill(const int* __restrict__ row, const int* __restrict__ col,
                       const float* __restrict__ w, int E) {
    int e = blockIdx.x * blockDim.x + threadIdx.x;
    if (e >= E) return;
    int r = row[e], c = col[e];
    float wv = w ? w[e] : 1.f;
    float nrm = rsqrtf((float)g_cnt[r]) * rsqrtf((float)g_cnt[NU + c]) * wv;
    int p0 = atomicAdd(&g_cur[r], 1);
    g_pl[p0] = make_float2(__int_as_float(NU + c), nrm);   // user's neighbor: item
    int p1 = atomicAdd(&g_cur[NU + c], 1);
    g_pl[p1] = make_float2(__int_as_float(r), nrm);        // item's neighbor: user
}

// e0 = fp16(emb), active nodes only. 8 threads per node.
__global__ void k_init(const float4* __restrict__ ue, const float4* __restrict__ ie) {
    int gid = blockIdx.x * blockDim.x + threadIdx.x;
    int node = gid >> 3;
    int t = gid & 7;
    if (node >= NN) return;
    if (g_cnt[node] == 0) return;
    const float4* src = (node < NU) ? (ue + (size_t)node * 16)
                                    : (ie + (size_t)(node - NU) * 16);
    float4 a = __ldg(src + t * 2);
    float4 b = __ldg(src + t * 2 + 1);
    g_e[0][node * 8 + t] = pack8(a, b);
}

// e[k] = e[k-1] + sum_nb norm * e[k-1][nb]. 8 threads/node, uint4 fp16 rows.
__global__ void k_gather(int k) {
    int gid = blockIdx.x * blockDim.x + threadIdx.x;
    int node = gid >> 3;
    int t = gid & 7;
    if (node >= NN) return;
    int cnt = g_cnt[node];
    if (cnt == 0) return;
    int beg = g_off[node];

    const uint4* __restrict__ src = g_e[k - 1];
    uint4* __restrict__ dst = g_e[k];

    float4 acc0, acc1;
    unpack8(__ldg(src + node * 8 + t), acc0, acc1);

    const float2* pl = g_pl + beg;
    int j = 0;
    for (; j + 2 <= cnt; j += 2) {
        float2 p0 = __ldg(pl + j);
        float2 p1 = __ldg(pl + j + 1);
        int i0 = __float_as_int(p0.x);
        int i1 = __float_as_int(p1.x);
        uint4 v0 = __ldg(src + i0 * 8 + t);
        uint4 v1 = __ldg(src + i1 * 8 + t);
        float4 a0, b0, a1, b1;
        unpack8(v0, a0, b0);
        unpack8(v1, a1, b1);
        acc0.x = fmaf(a0.x, p0.y, fmaf(a1.x, p1.y, acc0.x));
        acc0.y = fmaf(a0.y, p0.y, fmaf(a1.y, p1.y, acc0.y));
        acc0.z = fmaf(a0.z, p0.y, fmaf(a1.z, p1.y, acc0.z));
        acc0.w = fmaf(a0.w, p0.y, fmaf(a1.w, p1.y, acc0.w));
        acc1.x = fmaf(b0.x, p0.y, fmaf(b1.x, p1.y, acc1.x));
        acc1.y = fmaf(b0.y, p0.y, fmaf(b1.y, p1.y, acc1.y));
        acc1.z = fmaf(b0.z, p0.y, fmaf(b1.z, p1.y, acc1.z));
        acc1.w = fmaf(b0.w, p0.y, fmaf(b1.w, p1.y, acc1.w));
    }
    if (j < cnt) {
        float2 p0 = __ldg(pl + j);
        int i0 = __float_as_int(p0.x);
        uint4 v0 = __ldg(src + i0 * 8 + t);
        float4 a0, b0;
        unpack8(v0, a0, b0);
        acc0.x = fmaf(a0.x, p0.y, acc0.x);
        acc0.y = fmaf(a0.y, p0.y, acc0.y);
        acc0.z = fmaf(a0.z, p0.y, acc0.z);
        acc0.w = fmaf(a0.w, p0.y, acc0.w);
        acc1.x = fmaf(b0.x, p0.y, acc1.x);
        acc1.y = fmaf(b0.y, p0.y, acc1.y);
        acc1.z = fmaf(b0.z, p0.y, acc1.z);
        acc1.w = fmaf(b0.w, p0.y, acc1.w);
    }

    dst[node * 8 + t] = pack8(acc0, acc1);
}

// out = (emb + e1 + e2 + e3 + e4) * inv for active; out = emb for isolated.
__global__ void k_final(const float4* __restrict__ ue, const float4* __restrict__ ie,
                        float4* __restrict__ su, float4* __restrict__ si, float inv) {
    int gid = blockIdx.x * blockDim.x + threadIdx.x;
    int node = gid >> 3;
    int t = gid & 7;
    if (node >= NN) return;

    const float4* esrc;
    float4* osrc;
    int li;
    if (node < NU) { li = node;      esrc = ue; osrc = su; }
    else           { li = node - NU; esrc = ie; osrc = si; }

    float4 s0 = __ldg(esrc + (size_t)li * 16 + t * 2);
    float4 s1 = __ldg(esrc + (size_t)li * 16 + t * 2 + 1);

    if (g_cnt[node] != 0) {
#pragma unroll
        for (int k = 1; k <= 4; k++) {
            float4 a, b;
            unpack8(__ldg(&g_e[k][node * 8 + t]), a, b);
            s0.x += a.x; s0.y += a.y; s0.z += a.z; s0.w += a.w;
            s1.x += b.x; s1.y += b.y; s1.z += b.z; s1.w += b.w;
        }
        s0 = make_float4(s0.x * inv, s0.y * inv, s0.z * inv, s0.w * inv);
        s1 = make_float4(s1.x * inv, s1.y * inv, s1.z * inv, s1.w * inv);
    }
    osrc[(size_t)li * 16 + t * 2]     = s0;
    osrc[(size_t)li * 16 + t * 2 + 1] = s1;
}

extern "C" void kernel_launch(void* const* d_in, const int* in_sizes, int n_in,
                              void* d_out, int out_size) {
    const int*   ei  = (const int*)d_in[0];
    const int*   nei = (const int*)d_in[1];
    const float* ew  = (const float*)d_in[2];
    const float* up  = (const float*)d_in[3];
    const float* ip  = (const float*)d_in[4];
    const float* un  = (const float*)d_in[5];
    const float* inw = (const float*)d_in[6];
    float* out = (float*)d_out;

    const int Epos = in_sizes[0] / 2;
    const int Eneg = in_sizes[1] / 2;
    const float inv = 1.0f / 5.0f;

    struct Pass {
        const int* row; const int* col; const float* w; int E;
        const float* eu; const float* eiemb;
        float* su; float* si;
    };
    Pass passes[2];
    passes[0] = { ei,  ei  + Epos, ew,      Epos, up, ip,
                  out,                        out + (size_t)NU * D };
    passes[1] = { nei, nei + Eneg, nullptr, Eneg, un, inw,
                  out + (size_t)(NU + NI) * D, out + (size_t)(2 * NU + NI) * D };

    const int TB = 256;
    const int gNode = (NN + TB - 1) / TB;
    const int NB    = (NN + SCAN_ITEMS - 1) / SCAN_ITEMS;
    const int gW    = (NN * 8 + TB - 1) / TB;   // 8 threads per node

    for (int s = 0; s < 2; s++) {
        Pass P = passes[s];
        int gE = (P.E + TB - 1) / TB;

        k_zero_cnt<<<gNode, TB>>>();
        k_count<<<gE, TB>>>(P.row, P.col, P.E);
        k_scanA<<<NB, 256>>>(NN);
        k_scanB<<<1, MAX_NB>>>(NB);
        k_scanC<<<gNode, TB>>>(NN);
        k_fill<<<gE, TB>>>(P.row, P.col, P.w, P.E);
        k_init<<<gW, TB>>>((const float4*)P.eu, (const float4*)P.eiemb);

        for (int l = 1; l <= 4; l++)
            k_gather<<<gW, TB>>>(l);

        k_final<<<gW, TB>>>((const float4*)P.eu, (const float4*)P.eiemb,
                            (float4*)P.su, (float4*)P.si, inv);
    }
}